// round 14
// baseline (speedup 1.0000x reference)
#include <cuda_runtime.h>
#include <cmath>

#define CF 22
#define IPAD 24
#define KPAD 24
#define NM 9
#define TILE_W 16
#define TILE_H 16
#define NT 128
#define SCR_STRIDE 67
#define SM_W (CF * CF * IPAD)      // 11616
#define REGION_F 13568             // max(sK+scratch=13328, stage2=256*53)
#define TBL_F 704                  // 1408 ushorts

typedef unsigned long long ull;

__device__ float gWtp[CF * CF * IPAD];  // [k][j][i24]
__device__ float gK[NM * CF * KPAD];    // [m][i][k24]

// ---- packed f32x2 helpers (Blackwell FFMA2 path; only reachable via PTX) ----
__device__ __forceinline__ ull pk2(float lo, float hi) {
    ull r; asm("mov.b64 %0, {%1,%2};" : "=l"(r) : "f"(lo), "f"(hi)); return r;
}
__device__ __forceinline__ void upk2(ull v, float& a, float& b) {
    asm("mov.b64 {%0,%1}, %2;" : "=f"(a), "=f"(b) : "l"(v));
}
__device__ __forceinline__ ull pdup(float x) {
    ull r; asm("mov.b64 %0, {%1,%1};" : "=l"(r) : "f"(x)); return r;
}
__device__ __forceinline__ ull pfma(ull a, ull b, ull c) {
    ull r; asm("fma.rn.f32x2 %0, %1, %2, %3;" : "=l"(r) : "l"(a), "l"(b), "l"(c)); return r;
}
__device__ __forceinline__ ull pmul(ull a, ull b) {
    ull r; asm("mul.rn.f32x2 %0, %1, %2;" : "=l"(r) : "l"(a), "l"(b)); return r;
}
__device__ __forceinline__ ull padd(ull a, ull b) {
    ull r; asm("add.rn.f32x2 %0, %1, %2;" : "=l"(r) : "l"(a), "l"(b)); return r;
}

// ============================================================================
// Prep (unchanged)
// ============================================================================
__global__ void prep_kernel(const float* __restrict__ sh,
                            const float* __restrict__ cg_agg,
                            const float* __restrict__ cg_tp,
                            const float* __restrict__ w_agg,
                            const float* __restrict__ w_tp) {
    int gtid = blockIdx.x * blockDim.x + threadIdx.x;
    int nthr = gridDim.x * blockDim.x;
    for (int idx = gtid; idx < CF * CF * IPAD; idx += nthr) {
        int k = idx / (CF * IPAD);
        int r = idx - k * CF * IPAD;
        int j = r / IPAD;
        int i = r - j * IPAD;
        float v = 0.f;
        if (i < CF) {
            #pragma unroll
            for (int p = 0; p < 8; p++)
                v += w_tp[p] * cg_tp[((p * CF + i) * CF + j) * CF + k];
        }
        gWtp[idx] = v;
    }
    for (int idx = gtid; idx < CF * KPAD; idx += nthr) {
        int i = idx / KPAD;
        int k = idx - i * KPAD;
        float K0 = 0.f, K1 = 0.f, K2 = 0.f, K3 = 0.f;
        if (k < CF) {
            #pragma unroll
            for (int s = 0; s < 6; s++) {
                float wa = 0.f;
                #pragma unroll
                for (int p = 0; p < 6; p++)
                    wa += w_agg[p] * cg_agg[((p * CF + i) * 6 + s) * CF + k];
                K0 += wa * sh[0 * 6 + s];
                K1 += wa * sh[1 * 6 + s];
                K2 += wa * sh[2 * 6 + s];
                K3 += wa * sh[3 * 6 + s];
            }
        }
        gK[(0 * CF + i) * KPAD + k] = K0 + K1 + K2 + K3;
        gK[(1 * CF + i) * KPAD + k] = K0 + K2;
        gK[(2 * CF + i) * KPAD + k] = K0 + K1;
        gK[(3 * CF + i) * KPAD + k] = K0;
        gK[(4 * CF + i) * KPAD + k] = K1 + K3;
        gK[(5 * CF + i) * KPAD + k] = K1;
        gK[(6 * CF + i) * KPAD + k] = K2 + K3;
        gK[(7 * CF + i) * KPAD + k] = K2;
        gK[(8 * CF + i) * KPAD + k] = K3;
    }
}

// ctx pass with smem src (neighbor features)
template <int CAT>
__device__ __forceinline__ void ctx_pass(ull (&ctx2)[4][11], const ulonglong2* sK2,
                                         const float* src, int m) {
    #pragma unroll 2
    for (int i = 0; i < CF; i++) {
        ull fi2 = pdup(src[i]);
        const ulonglong2* row = sK2 + (m * CF + i) * 6;
        #pragma unroll
        for (int c = 0; c < 5; c++) {
            ulonglong2 t = row[c];
            ctx2[CAT][2 * c]     = pfma(fi2, t.x, ctx2[CAT][2 * c]);
            ctx2[CAT][2 * c + 1] = pfma(fi2, t.y, ctx2[CAT][2 * c + 1]);
        }
        ctx2[CAT][10] = pfma(fi2, row[5].x, ctx2[CAT][10]);
    }
}

// ctx pass with register src (self features, packed)
template <int CAT>
__device__ __forceinline__ void ctx_pass_reg(ull (&ctx2)[4][11], const ulonglong2* sK2,
                                             const ull (&fv)[11], int m) {
    #pragma unroll 2
    for (int ii = 0; ii < 11; ii++) {
        float fa, fb;
        upk2(fv[ii], fa, fb);
        {
            ull fi2 = pdup(fa);
            const ulonglong2* row = sK2 + (m * CF + 2 * ii) * 6;
            #pragma unroll
            for (int c = 0; c < 5; c++) {
                ulonglong2 t = row[c];
                ctx2[CAT][2 * c]     = pfma(fi2, t.x, ctx2[CAT][2 * c]);
                ctx2[CAT][2 * c + 1] = pfma(fi2, t.y, ctx2[CAT][2 * c + 1]);
            }
            ctx2[CAT][10] = pfma(fi2, row[5].x, ctx2[CAT][10]);
        }
        {
            ull fi2 = pdup(fb);
            const ulonglong2* row = sK2 + (m * CF + 2 * ii + 1) * 6;
            #pragma unroll
            for (int c = 0; c < 5; c++) {
                ulonglong2 t = row[c];
                ctx2[CAT][2 * c]     = pfma(fi2, t.x, ctx2[CAT][2 * c]);
                ctx2[CAT][2 * c + 1] = pfma(fi2, t.y, ctx2[CAT][2 * c + 1]);
            }
            ctx2[CAT][10] = pfma(fi2, row[5].x, ctx2[CAT][10]);
        }
    }
}

// full ctx for one pixel
__device__ __forceinline__ void compute_px(
    const float* __restrict__ f4, const float* __restrict__ f6, int H, int W,
    int h0, int w0, const ulonglong2* sK2, float* scr,
    ull (&f2)[11], float (&ctx)[4][CF], float (&selfArr)[CF]) {
    const int wR = min(w0 + 1, W - 1);
    const int hD = min(h0 + 1, H - 1);
    const int p00 = h0 * W + w0;
    const int p01 = h0 * W + wR;
    const int p10 = hD * W + w0;
    const int p11 = hD * W + wR;
    #pragma unroll
    for (int c = 0; c < 9; c++) selfArr[c] = f4[p00 * 9 + c];
    #pragma unroll
    for (int c = 0; c < 13; c++) selfArr[9 + c] = f6[p00 * 13 + c];
    #pragma unroll
    for (int kk = 0; kk < 11; kk++) f2[kk] = pk2(selfArr[2 * kk], selfArr[2 * kk + 1]);
    #pragma unroll
    for (int c = 0; c < 9; c++) {
        scr[c]      = f4[p01 * 9 + c];
        scr[CF + c] = f4[p10 * 9 + c];
        scr[2 * CF + c] = f4[p11 * 9 + c];
    }
    #pragma unroll
    for (int c = 0; c < 13; c++) {
        scr[9 + c]      = f6[p01 * 13 + c];
        scr[CF + 9 + c] = f6[p10 * 13 + c];
        scr[2 * CF + 9 + c] = f6[p11 * 13 + c];
    }

    ull ctx2[4][11];
    #pragma unroll
    for (int c4 = 0; c4 < 4; c4++)
        #pragma unroll
        for (int kk = 0; kk < 11; kk++) ctx2[c4][kk] = 0ULL;

    ctx_pass_reg<0>(ctx2, sK2, f2, 0);
    ctx_pass_reg<1>(ctx2, sK2, f2, 1);
    ctx_pass_reg<2>(ctx2, sK2, f2, 2);
    ctx_pass_reg<3>(ctx2, sK2, f2, 3);
    ctx_pass<1>(ctx2, sK2, scr, 4);
    ctx_pass<3>(ctx2, sK2, scr, 5);
    ctx_pass<2>(ctx2, sK2, scr + CF, 6);
    ctx_pass<3>(ctx2, sK2, scr + CF, 7);
    ctx_pass<3>(ctx2, sK2, scr + 2 * CF, 8);

    #pragma unroll
    for (int c4 = 0; c4 < 4; c4++)
        #pragma unroll
        for (int kk = 0; kk < 11; kk++) {
            float a, b;
            upk2(ctx2[c4][kk], a, b);
            ctx[c4][2 * kk] = a;
            ctx[c4][2 * kk + 1] = b;
        }
}

// ============================================================================
// Main kernel: 16x16 low-res tile, NT=128, 2 px/thread (pxB = pxA + 128).
// W rows loaded ONCE per (k,j) feed BOTH pixels' dot chains: LDS/px halved,
// 2x ILP per warp. smem = sW 46.5K + region 54.3K (sK+scratch, then stage)
// + tables 2.8K = 103.5KB -> 2 blocks/SM (8 warps). Reg cap 256.
// ============================================================================
__global__ void __launch_bounds__(NT, 2)
main_kernel(const float* __restrict__ f4, const float* __restrict__ f6,
            float* __restrict__ out, int H, int W) {
    extern __shared__ float smem[];
    float* sW = smem;                       // SM_W floats
    float* region = smem + SM_W;            // REGION_F floats
    unsigned short* tbl4 = (unsigned short*)(region + REGION_F);  // 576
    unsigned short* tbl6 = tbl4 + 576;                            // 832
    const int tid = threadIdx.x;

    for (int idx = tid; idx < SM_W; idx += NT) sW[idx] = gWtp[idx];
    {
        float* sK = region;
        for (int idx = tid; idx < NM * CF * KPAD; idx += NT) sK[idx] = gK[idx];
    }
    // drain tables (stage strides: phase1=37, phase2=53)
    for (int ee = tid; ee < 576; ee += NT) {
        int px = ee / 9;
        int c = ee - px * 9;
        int b = px & 3;
        int lxr = px >> 2;
        int cat = (b < 3) ? 0 : 1;   // a==3 rows: +18 (cat 2/3)
        tbl4[ee] = (unsigned short)(lxr * 37 + cat * 9 + c);
    }
    for (int ee = tid; ee < 832; ee += NT) {
        int px = ee / 13;
        int c = ee - px * 13;
        int b = px & 3;
        int lxr = px >> 2;
        int cat = (b < 3) ? 0 : 1;   // a==3 rows: +26
        tbl6[ee] = (unsigned short)(lxr * 53 + cat * 13 + c);
    }
    __syncthreads();

    const int tiles_x = W / TILE_W;
    const int tx0 = (blockIdx.x % tiles_x) * TILE_W;
    const int ty0 = (blockIdx.x / tiles_x) * TILE_H;
    const int lx = tid % TILE_W;
    const int ly = tid / TILE_W;            // 0..7

    // ---- ctx phase for both pixels (scratch time-shared per thread) ----
    const ulonglong2* sK2 = (const ulonglong2*)region;
    float* scr = region + NM * CF * KPAD + tid * SCR_STRIDE;
    ull f2A[11], f2B[11];
    float ctxA[4][CF], ctxB[4][CF];
    float selfA[CF], selfB[CF];
    compute_px(f4, f6, H, W, ty0 + ly,     tx0 + lx, sK2, scr, f2A, ctxA, selfA);
    compute_px(f4, f6, H, W, ty0 + ly + 8, tx0 + lx, sK2, scr, f2B, ctxB, selfB);
    __syncthreads();  // sK + scratch dead -> region becomes stage

    const ulonglong2* sW2 = (const ulonglong2*)sW;
    const int Wr = W * 4;

    // ================= phase 1: k = 0..8 -> out4 =================
    {
        float* mA = region + tid * 37;
        float* mB = region + (tid + NT) * 37;
        #pragma unroll 1
        for (int k = 0; k < 9; k++) {
            float oA0 = 0.f, oA1 = 0.f, oA2 = 0.f, oA3 = 0.f;
            float oB0 = 0.f, oB1 = 0.f, oB2 = 0.f, oB3 = 0.f;
            const ulonglong2* wbase = sW2 + k * (CF * 6);
            #pragma unroll
            for (int j = 0; j < CF; j++) {
                const ulonglong2* wr = wbase + j * 6;
                ulonglong2 t0 = wr[0], t1 = wr[1], t2 = wr[2];
                ulonglong2 t3 = wr[3], t4 = wr[4];
                ull t10 = wr[5].x;
                ull va = pmul(f2A[0], t0.x);
                ull vc = pmul(f2B[0], t0.x);
                ull vb = pmul(f2A[1], t0.y);
                ull vd = pmul(f2B[1], t0.y);
                va = pfma(f2A[2], t1.x, va);  vc = pfma(f2B[2], t1.x, vc);
                vb = pfma(f2A[3], t1.y, vb);  vd = pfma(f2B[3], t1.y, vd);
                va = pfma(f2A[4], t2.x, va);  vc = pfma(f2B[4], t2.x, vc);
                vb = pfma(f2A[5], t2.y, vb);  vd = pfma(f2B[5], t2.y, vd);
                va = pfma(f2A[6], t3.x, va);  vc = pfma(f2B[6], t3.x, vc);
                vb = pfma(f2A[7], t3.y, vb);  vd = pfma(f2B[7], t3.y, vd);
                va = pfma(f2A[8], t4.x, va);  vc = pfma(f2B[8], t4.x, vc);
                vb = pfma(f2A[9], t4.y, vb);  vd = pfma(f2B[9], t4.y, vd);
                va = pfma(f2A[10], t10, va);  vc = pfma(f2B[10], t10, vc);
                ull vpA = padd(va, vb);
                ull vpB = padd(vc, vd);
                float a, b;
                upk2(vpA, a, b);
                float vA = a + b;
                upk2(vpB, a, b);
                float vB = a + b;
                oA0 += vA * ctxA[0][j];  oB0 += vB * ctxB[0][j];
                oA1 += vA * ctxA[1][j];  oB1 += vB * ctxB[1][j];
                oA2 += vA * ctxA[2][j];  oB2 += vB * ctxB[2][j];
                oA3 += vA * ctxA[3][j];  oB3 += vB * ctxB[3][j];
            }
            float xA = selfA[k], xB = selfB[k];
            mA[0 * 9 + k] = oA0 + xA;  mB[0 * 9 + k] = oB0 + xB;
            mA[1 * 9 + k] = oA1 + xA;  mB[1 * 9 + k] = oB1 + xB;
            mA[2 * 9 + k] = oA2 + xA;  mB[2 * 9 + k] = oB2 + xB;
            mA[3 * 9 + k] = oA3 + xA;  mB[3 * 9 + k] = oB3 + xB;
        }
    }
    __syncthreads();
    {   // drain out4: 64 hi-res rows x 144 float4
        const int QR = 144;
        for (int idx = tid; idx < TILE_H * 4 * QR; idx += NT) {
            int y = idx / QR;
            int q = idx - y * QR;
            int py = y >> 2;
            int base = py * (TILE_W * 37) + (((y & 3) == 3) ? 18 : 0);
            ushort4 tb = *(const ushort4*)(tbl4 + q * 4);
            float4 v = make_float4(region[base + tb.x], region[base + tb.y],
                                   region[base + tb.z], region[base + tb.w]);
            int gy = ty0 * 4 + y;
            float4* dst = (float4*)(out + ((size_t)gy * Wr + (size_t)tx0 * 4) * 9);
            dst[q] = v;
        }
    }
    __syncthreads();

    // ================= phase 2: k = 9..21 -> out6 =================
    {
        float* mA = region + tid * 53;
        float* mB = region + (tid + NT) * 53;
        #pragma unroll 1
        for (int k = 9; k < CF; k++) {
            float oA0 = 0.f, oA1 = 0.f, oA2 = 0.f, oA3 = 0.f;
            float oB0 = 0.f, oB1 = 0.f, oB2 = 0.f, oB3 = 0.f;
            const ulonglong2* wbase = sW2 + k * (CF * 6);
            #pragma unroll
            for (int j = 0; j < CF; j++) {
                const ulonglong2* wr = wbase + j * 6;
                ulonglong2 t0 = wr[0], t1 = wr[1], t2 = wr[2];
                ulonglong2 t3 = wr[3], t4 = wr[4];
                ull t10 = wr[5].x;
                ull va = pmul(f2A[0], t0.x);
                ull vc = pmul(f2B[0], t0.x);
                ull vb = pmul(f2A[1], t0.y);
                ull vd = pmul(f2B[1], t0.y);
                va = pfma(f2A[2], t1.x, va);  vc = pfma(f2B[2], t1.x, vc);
                vb = pfma(f2A[3], t1.y, vb);  vd = pfma(f2B[3], t1.y, vd);
                va = pfma(f2A[4], t2.x, va);  vc = pfma(f2B[4], t2.x, vc);
                vb = pfma(f2A[5], t2.y, vb);  vd = pfma(f2B[5], t2.y, vd);
                va = pfma(f2A[6], t3.x, va);  vc = pfma(f2B[6], t3.x, vc);
                vb = pfma(f2A[7], t3.y, vb);  vd = pfma(f2B[7], t3.y, vd);
                va = pfma(f2A[8], t4.x, va);  vc = pfma(f2B[8], t4.x, vc);
                vb = pfma(f2A[9], t4.y, vb);  vd = pfma(f2B[9], t4.y, vd);
                va = pfma(f2A[10], t10, va);  vc = pfma(f2B[10], t10, vc);
                ull vpA = padd(va, vb);
                ull vpB = padd(vc, vd);
                float a, b;
                upk2(vpA, a, b);
                float vA = a + b;
                upk2(vpB, a, b);
                float vB = a + b;
                oA0 += vA * ctxA[0][j];  oB0 += vB * ctxB[0][j];
                oA1 += vA * ctxA[1][j];  oB1 += vB * ctxB[1][j];
                oA2 += vA * ctxA[2][j];  oB2 += vB * ctxB[2][j];
                oA3 += vA * ctxA[3][j];  oB3 += vB * ctxB[3][j];
            }
            int kc = k - 9;
            float xA = selfA[k], xB = selfB[k];
            mA[0 * 13 + kc] = oA0 + xA;  mB[0 * 13 + kc] = oB0 + xB;
            mA[1 * 13 + kc] = oA1 + xA;  mB[1 * 13 + kc] = oB1 + xB;
            mA[2 * 13 + kc] = oA2 + xA;  mB[2 * 13 + kc] = oB2 + xB;
            mA[3 * 13 + kc] = oA3 + xA;  mB[3 * 13 + kc] = oB3 + xB;
        }
    }
    __syncthreads();
    {   // drain out6: 64 hi-res rows x 208 float4
        const size_t N9 = (size_t)H * W * 16 * 9;
        const int QR = 208;
        for (int idx = tid; idx < TILE_H * 4 * QR; idx += NT) {
            int y = idx / QR;
            int q = idx - y * QR;
            int py = y >> 2;
            int base = py * (TILE_W * 53) + (((y & 3) == 3) ? 26 : 0);
            ushort4 tb = *(const ushort4*)(tbl6 + q * 4);
            float4 v = make_float4(region[base + tb.x], region[base + tb.y],
                                   region[base + tb.z], region[base + tb.w]);
            int gy = ty0 * 4 + y;
            float4* dst = (float4*)(out + N9 + ((size_t)gy * Wr + (size_t)tx0 * 4) * 13);
            dst[q] = v;
        }
    }
}

extern "C" void kernel_launch(void* const* d_in, const int* in_sizes, int n_in,
                              void* d_out, int out_size) {
    const float* f4     = (const float*)d_in[0];
    const float* f6     = (const float*)d_in[1];
    const float* sh     = (const float*)d_in[2];
    const float* cg_agg = (const float*)d_in[3];
    const float* cg_tp  = (const float*)d_in[4];
    const float* w_agg  = (const float*)d_in[5];
    const float* w_tp   = (const float*)d_in[6];
    float* out = (float*)d_out;

    int HW = in_sizes[0] / 9;
    int W = (int)(sqrt((double)HW) + 0.5);
    int H = HW / W;

    prep_kernel<<<96, 128>>>(sh, cg_agg, cg_tp, w_agg, w_tp);

    int smemB = (SM_W + REGION_F + TBL_F) * (int)sizeof(float);  // 103,552 B
    cudaFuncSetAttribute(main_kernel, cudaFuncAttributeMaxDynamicSharedMemorySize, smemB);
    int nblocks = (W / TILE_W) * (H / TILE_H);
    main_kernel<<<nblocks, NT, smemB>>>(f4, f6, out, H, W);
}

// round 16
// speedup vs baseline: 1.0023x; 1.0023x over previous
#include <cuda_runtime.h>
#include <cmath>

#define CF 22
#define IPAD 24
#define KPAD 24
#define NM 9
#define TILE_W 16
#define TILE_H 8
#define NT 128

typedef unsigned long long ull;

// Precomputed weighted tensors (prep kernel output)
__device__ float gWtp[CF * CF * IPAD];  // [k][j][i24]
__device__ float gK[NM * CF * KPAD];    // [m][i][k24]

// ---- packed f32x2 helpers (Blackwell FFMA2 path; only reachable via PTX) ----
__device__ __forceinline__ ull pk2(float lo, float hi) {
    ull r; asm("mov.b64 %0, {%1,%2};" : "=l"(r) : "f"(lo), "f"(hi)); return r;
}
__device__ __forceinline__ void upk2(ull v, float& a, float& b) {
    asm("mov.b64 {%0,%1}, %2;" : "=f"(a), "=f"(b) : "l"(v));
}
__device__ __forceinline__ ull pdup(float x) {
    ull r; asm("mov.b64 %0, {%1,%1};" : "=l"(r) : "f"(x)); return r;
}
__device__ __forceinline__ ull pfma(ull a, ull b, ull c) {
    ull r; asm("fma.rn.f32x2 %0, %1, %2, %3;" : "=l"(r) : "l"(a), "l"(b), "l"(c)); return r;
}
__device__ __forceinline__ ull pmul(ull a, ull b) {
    ull r; asm("mul.rn.f32x2 %0, %1, %2;" : "=l"(r) : "l"(a), "l"(b)); return r;
}
__device__ __forceinline__ ull padd(ull a, ull b) {
    ull r; asm("add.rn.f32x2 %0, %1, %2;" : "=l"(r) : "l"(a), "l"(b)); return r;
}

// ============================================================================
// Prep: fold learned weights into Wtp and the 9 context matrices.
// m: 0:K0+K1+K2+K3  1:K0+K2  2:K0+K1  3:K0  4:K1+K3  5:K1  6:K2+K3  7:K2  8:K3
// ============================================================================
__global__ void prep_kernel(const float* __restrict__ sh,
                            const float* __restrict__ cg_agg,
                            const float* __restrict__ cg_tp,
                            const float* __restrict__ w_agg,
                            const float* __restrict__ w_tp) {
    int gtid = blockIdx.x * blockDim.x + threadIdx.x;
    int nthr = gridDim.x * blockDim.x;
    for (int idx = gtid; idx < CF * CF * IPAD; idx += nthr) {
        int k = idx / (CF * IPAD);
        int r = idx - k * CF * IPAD;
        int j = r / IPAD;
        int i = r - j * IPAD;
        float v = 0.f;
        if (i < CF) {
            #pragma unroll
            for (int p = 0; p < 8; p++)
                v += w_tp[p] * cg_tp[((p * CF + i) * CF + j) * CF + k];
        }
        gWtp[idx] = v;
    }
    for (int idx = gtid; idx < CF * KPAD; idx += nthr) {
        int i = idx / KPAD;
        int k = idx - i * KPAD;
        float K0 = 0.f, K1 = 0.f, K2 = 0.f, K3 = 0.f;
        if (k < CF) {
            #pragma unroll
            for (int s = 0; s < 6; s++) {
                float wa = 0.f;
                #pragma unroll
                for (int p = 0; p < 6; p++)
                    wa += w_agg[p] * cg_agg[((p * CF + i) * 6 + s) * CF + k];
                K0 += wa * sh[0 * 6 + s];
                K1 += wa * sh[1 * 6 + s];
                K2 += wa * sh[2 * 6 + s];
                K3 += wa * sh[3 * 6 + s];
            }
        }
        gK[(0 * CF + i) * KPAD + k] = K0 + K1 + K2 + K3;
        gK[(1 * CF + i) * KPAD + k] = K0 + K2;
        gK[(2 * CF + i) * KPAD + k] = K0 + K1;
        gK[(3 * CF + i) * KPAD + k] = K0;
        gK[(4 * CF + i) * KPAD + k] = K1 + K3;
        gK[(5 * CF + i) * KPAD + k] = K1;
        gK[(6 * CF + i) * KPAD + k] = K2 + K3;
        gK[(7 * CF + i) * KPAD + k] = K2;
        gK[(8 * CF + i) * KPAD + k] = K3;
    }
}

// Context accumulation pass: ctx2[CAT][*] += src[i] * sK[m][i][*]
template <int CAT>
__device__ __forceinline__ void ctx_pass(ull (&ctx2)[4][11], const ulonglong2* sK2,
                                         const float* src, int m) {
    #pragma unroll 2
    for (int i = 0; i < CF; i++) {
        ull fi2 = pdup(src[i]);
        const ulonglong2* row = sK2 + (m * CF + i) * 6;
        #pragma unroll
        for (int c = 0; c < 5; c++) {
            ulonglong2 t = row[c];
            ctx2[CAT][2 * c]     = pfma(fi2, t.x, ctx2[CAT][2 * c]);
            ctx2[CAT][2 * c + 1] = pfma(fi2, t.y, ctx2[CAT][2 * c + 1]);
        }
        ull t10 = row[5].x;
        ctx2[CAT][10] = pfma(fi2, t10, ctx2[CAT][10]);
    }
}

// One dot chain: v = sum_i f2[i] * W[k][j][i]  (returns scalar)
__device__ __forceinline__ float dotw(const ull (&f2)[11], const ulonglong2* wr) {
    ulonglong2 t0 = wr[0], t1 = wr[1], t2 = wr[2];
    ull va = pmul(f2[0], t0.x);
    ull vb = pmul(f2[1], t0.y);
    va = pfma(f2[2], t1.x, va);
    vb = pfma(f2[3], t1.y, vb);
    va = pfma(f2[4], t2.x, va);
    vb = pfma(f2[5], t2.y, vb);
    ulonglong2 t3 = wr[3], t4 = wr[4];
    ull t10 = wr[5].x;
    va = pfma(f2[6], t3.x, va);
    vb = pfma(f2[7], t3.y, vb);
    va = pfma(f2[8], t4.x, va);
    vb = pfma(f2[9], t4.y, vb);
    va = pfma(f2[10], t10, va);
    ull vp = padd(va, vb);
    float a, b;
    upk2(vp, a, b);
    return a + b;
}

// ============================================================================
// Main kernel (R12 champion + dual-k inner loop for 2x ILP):
//   smem = sW (45.4KB) + sK (18.6KB) + stage (44.5KB) + tables (2.8KB)
//        = 111.2KB -> 2 blocks/SM, grid=512 (good wave balance).
//   k-loop: 11 iterations, each processing kA=kk and kB=kk+11 with fully
//   independent W streams + dot chains, SHARING the 88 ctx registers.
//   Drain: table-driven, no div, no LDG (residual folded into the stage).
// ============================================================================
__global__ void __launch_bounds__(NT, 2)
main_kernel(const float* __restrict__ f4, const float* __restrict__ f6,
            float* __restrict__ out, int H, int W) {
    extern __shared__ float smem[];
    float* sW = smem;                      // CF*CF*IPAD
    float* sK = smem + CF * CF * IPAD;     // NM*CF*KPAD
    float* stg = sK + NM * CF * KPAD;      // NT*89 (stride 89 -> conflict-free)
    unsigned short* tbl4 = (unsigned short*)(stg + NT * 89);  // 576 entries
    unsigned short* tbl6 = tbl4 + 576;                        // 832 entries
    const int tid = threadIdx.x;

    for (int idx = tid; idx < CF * CF * IPAD; idx += NT) sW[idx] = gWtp[idx];
    for (int idx = tid; idx < NM * CF * KPAD; idx += NT) sK[idx] = gK[idx];
    // index tables: stage offset for each element of one hi-res row image
    for (int ee = tid; ee < 576; ee += NT) {
        int px = ee / 9;
        int c = ee - px * 9;
        int b = px & 3;
        int lxr = px >> 2;
        int cat = (b < 3) ? 0 : 1;   // a==3 rows: same entry + 44 (cat 2/3)
        tbl4[ee] = (unsigned short)(lxr * 89 + cat * CF + c);
    }
    for (int ee = tid; ee < 832; ee += NT) {
        int px = ee / 13;
        int c = ee - px * 13;
        int b = px & 3;
        int lxr = px >> 2;
        int cat = (b < 3) ? 0 : 1;
        tbl6[ee] = (unsigned short)(lxr * 89 + cat * CF + 9 + c);
    }
    __syncthreads();

    const int tiles_x = W / TILE_W;
    const int tx0 = (blockIdx.x % tiles_x) * TILE_W;
    const int ty0 = (blockIdx.x / tiles_x) * TILE_H;
    const int lx = tid % TILE_W;
    const int ly = tid / TILE_W;
    const int w0 = tx0 + lx;
    const int h0 = ty0 + ly;
    const int wR = min(w0 + 1, W - 1);
    const int hD = min(h0 + 1, H - 1);
    const int p00 = h0 * W + w0;
    const int p01 = h0 * W + wR;
    const int p10 = hD * W + w0;
    const int p11 = hD * W + wR;

    // ---- preload features: self -> packed regs, all 4 sources -> per-thread stage ----
    float* myst = stg + tid * 89;
    ull f2[11];
    {
        float xv[CF];
        #pragma unroll
        for (int c = 0; c < CF; c++) {
            xv[c] = (c < 9) ? f4[p00 * 9 + c] : f6[p00 * 13 + (c - 9)];
            myst[c] = xv[c];
        }
        #pragma unroll
        for (int kk = 0; kk < 11; kk++) f2[kk] = pk2(xv[2 * kk], xv[2 * kk + 1]);
        #pragma unroll
        for (int c = 0; c < CF; c++) {
            myst[1 * CF + c] = (c < 9) ? f4[p01 * 9 + c] : f6[p01 * 13 + (c - 9)];
            myst[2 * CF + c] = (c < 9) ? f4[p10 * 9 + c] : f6[p10 * 13 + (c - 9)];
            myst[3 * CF + c] = (c < 9) ? f4[p11 * 9 + c] : f6[p11 * 13 + (c - 9)];
        }
    }

    // ---- 4 context vectors (cat 0:interior 1:right-edge 2:bottom-edge 3:corner) ----
    ull ctx2[4][11];
    #pragma unroll
    for (int c4 = 0; c4 < 4; c4++)
        #pragma unroll
        for (int kk = 0; kk < 11; kk++) ctx2[c4][kk] = 0ULL;

    const ulonglong2* sK2 = (const ulonglong2*)sK;
    ctx_pass<0>(ctx2, sK2, myst, 0);
    ctx_pass<1>(ctx2, sK2, myst, 1);
    ctx_pass<2>(ctx2, sK2, myst, 2);
    ctx_pass<3>(ctx2, sK2, myst, 3);
    ctx_pass<1>(ctx2, sK2, myst + CF, 4);
    ctx_pass<3>(ctx2, sK2, myst + CF, 5);
    ctx_pass<2>(ctx2, sK2, myst + 2 * CF, 6);
    ctx_pass<3>(ctx2, sK2, myst + 2 * CF, 7);
    ctx_pass<3>(ctx2, sK2, myst + 3 * CF, 8);

    // unpack ctx to 88 scalar regs (upk2 aliases to reg pairs -> free)
    float ctx[4][CF];
    #pragma unroll
    for (int c4 = 0; c4 < 4; c4++)
        #pragma unroll
        for (int kk = 0; kk < 11; kk++) {
            float a, b;
            upk2(ctx2[c4][kk], a, b);
            ctx[c4][2 * kk] = a;
            ctx[c4][2 * kk + 1] = b;
        }

    // ---- bilinear: dual-k inner loop (kA=kk, kB=kk+11), shared ctx regs ----
    const ulonglong2* sW2 = (const ulonglong2*)sW;
    #pragma unroll 1
    for (int kk = 0; kk < 11; kk++) {
        const int kA = kk;
        const int kB = kk + 11;
        float oA0 = 0.f, oA1 = 0.f, oA2 = 0.f, oA3 = 0.f;
        float oB0 = 0.f, oB1 = 0.f, oB2 = 0.f, oB3 = 0.f;
        const ulonglong2* wbA = sW2 + kA * (CF * 6);
        const ulonglong2* wbB = sW2 + kB * (CF * 6);
        #pragma unroll
        for (int j = 0; j < CF; j++) {
            float vA = dotw(f2, wbA + j * 6);
            float vB = dotw(f2, wbB + j * 6);
            oA0 += vA * ctx[0][j];   oB0 += vB * ctx[0][j];
            oA1 += vA * ctx[1][j];   oB1 += vB * ctx[1][j];
            oA2 += vA * ctx[2][j];   oB2 += vB * ctx[2][j];
            oA3 += vA * ctx[3][j];   oB3 += vB * ctx[3][j];
        }
        // residual fold: self features still resident in myst[0..21]
        float xA = myst[kA];
        float xB = myst[kB];
        myst[0 * CF + kA] = oA0 + xA;
        myst[1 * CF + kA] = oA1 + xA;
        myst[2 * CF + kA] = oA2 + xA;
        myst[3 * CF + kA] = oA3 + xA;
        myst[0 * CF + kB] = oB0 + xB;
        myst[1 * CF + kB] = oB1 + xB;
        myst[2 * CF + kB] = oB2 + xB;
        myst[3 * CF + kB] = oB3 + xB;
    }
    __syncthreads();

    // ---- table-driven drain: pure smem->gmem copy, no div, no LDG ----
    const int Wr = W * 4;
    {   // out4: 64 px * 9 floats = 144 float4 per hi-res row
        const int QR = 144;
        for (int idx = tid; idx < TILE_H * 4 * QR; idx += NT) {
            int y = idx / QR;
            int q = idx - y * QR;
            int py = y >> 2;
            int base = py * (TILE_W * 89) + (((y & 3) == 3) ? 2 * CF : 0);
            ushort4 tb = *(const ushort4*)(tbl4 + q * 4);
            float4 v = make_float4(stg[base + tb.x], stg[base + tb.y],
                                   stg[base + tb.z], stg[base + tb.w]);
            int gy = ty0 * 4 + y;
            float4* dst = (float4*)(out + ((size_t)gy * Wr + (size_t)tx0 * 4) * 9);
            dst[q] = v;
        }
    }
    {   // out6: 64 px * 13 floats = 208 float4 per hi-res row
        const size_t N9 = (size_t)H * W * 16 * 9;
        const int QR = 208;
        for (int idx = tid; idx < TILE_H * 4 * QR; idx += NT) {
            int y = idx / QR;
            int q = idx - y * QR;
            int py = y >> 2;
            int base = py * (TILE_W * 89) + (((y & 3) == 3) ? 2 * CF : 0);
            ushort4 tb = *(const ushort4*)(tbl6 + q * 4);
            float4 v = make_float4(stg[base + tb.x], stg[base + tb.y],
                                   stg[base + tb.z], stg[base + tb.w]);
            int gy = ty0 * 4 + y;
            float4* dst = (float4*)(out + N9 + ((size_t)gy * Wr + (size_t)tx0 * 4) * 13);
            dst[q] = v;
        }
    }
}

extern "C" void kernel_launch(void* const* d_in, const int* in_sizes, int n_in,
                              void* d_out, int out_size) {
    const float* f4     = (const float*)d_in[0];
    const float* f6     = (const float*)d_in[1];
    const float* sh     = (const float*)d_in[2];
    const float* cg_agg = (const float*)d_in[3];
    const float* cg_tp  = (const float*)d_in[4];
    const float* w_agg  = (const float*)d_in[5];
    const float* w_tp   = (const float*)d_in[6];
    float* out = (float*)d_out;

    int HW = in_sizes[0] / 9;
    int W = (int)(sqrt((double)HW) + 0.5);
    int H = HW / W;

    prep_kernel<<<96, 128>>>(sh, cg_agg, cg_tp, w_agg, w_tp);

    // floats: sW 11616 + sK 4752 + stage 11392, then 1408 ushorts (704 floats)
    int smemB = (CF * CF * IPAD + NM * CF * KPAD + NT * 89 + 704) * (int)sizeof(float);
    cudaFuncSetAttribute(main_kernel, cudaFuncAttributeMaxDynamicSharedMemorySize, smemB);
    int nblocks = HW / NT;
    main_kernel<<<nblocks, NT, smemB>>>(f4, f6, out, H, W);
}

// round 17
// speedup vs baseline: 1.1056x; 1.1031x over previous
#include <cuda_runtime.h>
#include <cmath>

#define CF 22
#define IPAD 24
#define KPAD 24
#define NM 4
#define TILE_W 16
#define TILE_H 8
#define NT 128

typedef unsigned long long ull;

// Precomputed weighted tensors (prep kernel output)
__device__ float gWtp[CF * CF * IPAD];  // [k][j][i24]
__device__ float gK[NM * CF * KPAD];    // [m][i][k24]: m0,m4(K1+K3),m6(K2+K3),K3

// ---- packed f32x2 helpers (Blackwell FFMA2 path; only reachable via PTX) ----
__device__ __forceinline__ ull pk2(float lo, float hi) {
    ull r; asm("mov.b64 %0, {%1,%2};" : "=l"(r) : "f"(lo), "f"(hi)); return r;
}
__device__ __forceinline__ void upk2(ull v, float& a, float& b) {
    asm("mov.b64 {%0,%1}, %2;" : "=f"(a), "=f"(b) : "l"(v));
}
__device__ __forceinline__ ull pdup(float x) {
    ull r; asm("mov.b64 %0, {%1,%1};" : "=l"(r) : "f"(x)); return r;
}
__device__ __forceinline__ ull pfma(ull a, ull b, ull c) {
    ull r; asm("fma.rn.f32x2 %0, %1, %2, %3;" : "=l"(r) : "l"(a), "l"(b), "l"(c)); return r;
}
__device__ __forceinline__ ull pmul(ull a, ull b) {
    ull r; asm("mul.rn.f32x2 %0, %1, %2;" : "=l"(r) : "l"(a), "l"(b)); return r;
}
__device__ __forceinline__ ull padd(ull a, ull b) {
    ull r; asm("add.rn.f32x2 %0, %1, %2;" : "=l"(r) : "l"(a), "l"(b)); return r;
}

// ============================================================================
// Prep: fold learned weights into Wtp and the 4 difference-basis matrices:
//   m0 = K0+K1+K2+K3,  m1 = K1+K3,  m2 = K2+K3,  m3 = K3
// ctx0 = m0 f00; ctx1 = ctx0 + m1 dR; ctx2 = ctx0 + m2 dD;
// ctx3 = ctx0 + m1 dR + m2 dD + m3 (f00+fX-fR-fD)
// ============================================================================
__global__ void prep_kernel(const float* __restrict__ sh,
                            const float* __restrict__ cg_agg,
                            const float* __restrict__ cg_tp,
                            const float* __restrict__ w_agg,
                            const float* __restrict__ w_tp) {
    int gtid = blockIdx.x * blockDim.x + threadIdx.x;
    int nthr = gridDim.x * blockDim.x;
    for (int idx = gtid; idx < CF * CF * IPAD; idx += nthr) {
        int k = idx / (CF * IPAD);
        int r = idx - k * CF * IPAD;
        int j = r / IPAD;
        int i = r - j * IPAD;
        float v = 0.f;
        if (i < CF) {
            #pragma unroll
            for (int p = 0; p < 8; p++)
                v += w_tp[p] * cg_tp[((p * CF + i) * CF + j) * CF + k];
        }
        gWtp[idx] = v;
    }
    for (int idx = gtid; idx < CF * KPAD; idx += nthr) {
        int i = idx / KPAD;
        int k = idx - i * KPAD;
        float K0 = 0.f, K1 = 0.f, K2 = 0.f, K3 = 0.f;
        if (k < CF) {
            #pragma unroll
            for (int s = 0; s < 6; s++) {
                float wa = 0.f;
                #pragma unroll
                for (int p = 0; p < 6; p++)
                    wa += w_agg[p] * cg_agg[((p * CF + i) * 6 + s) * CF + k];
                K0 += wa * sh[0 * 6 + s];
                K1 += wa * sh[1 * 6 + s];
                K2 += wa * sh[2 * 6 + s];
                K3 += wa * sh[3 * 6 + s];
            }
        }
        gK[(0 * CF + i) * KPAD + k] = K0 + K1 + K2 + K3;
        gK[(1 * CF + i) * KPAD + k] = K1 + K3;
        gK[(2 * CF + i) * KPAD + k] = K2 + K3;
        gK[(3 * CF + i) * KPAD + k] = K3;
    }
}

// Context accumulation pass: ctx2[CAT][*] += src[i] * sK[m][i][*]
template <int CAT>
__device__ __forceinline__ void ctx_pass(ull (&ctx2)[4][11], const ulonglong2* sK2,
                                         const float* src, int m) {
    #pragma unroll 2
    for (int i = 0; i < CF; i++) {
        ull fi2 = pdup(src[i]);
        const ulonglong2* row = sK2 + (m * CF + i) * 6;
        #pragma unroll
        for (int c = 0; c < 5; c++) {
            ulonglong2 t = row[c];
            ctx2[CAT][2 * c]     = pfma(fi2, t.x, ctx2[CAT][2 * c]);
            ctx2[CAT][2 * c + 1] = pfma(fi2, t.y, ctx2[CAT][2 * c + 1]);
        }
        ull t10 = row[5].x;
        ctx2[CAT][10] = pfma(fi2, t10, ctx2[CAT][10]);
    }
}

// ============================================================================
// Main kernel (R12 champion + 4-matvec difference-basis ctx phase):
//   smem = sW (45.4KB) + sK (8.3KB) + stage (44.5KB) + tables (2.8KB)
//        = 101KB -> 2 blocks/SM.
//   ctx phase: 4 matvecs (m0 f00, m1 dR, m2 dD, m3 d2) instead of 9:
//   -660 LDS.128 and -1320 FFMA2 per thread. Bilinear accumulates against
//   (ctx0, e1, e2, e3); cat outputs derived by adds in the k-epilogue.
//   Drain: table-driven, no div, no LDG (residual folded into the stage).
// ============================================================================
__global__ void __launch_bounds__(NT, 2)
main_kernel(const float* __restrict__ f4, const float* __restrict__ f6,
            float* __restrict__ out, int H, int W) {
    extern __shared__ float smem[];
    float* sW = smem;                      // CF*CF*IPAD
    float* sK = smem + CF * CF * IPAD;     // NM*CF*KPAD (4 matrices)
    float* stg = sK + NM * CF * KPAD;      // NT*89 (stride 89 -> conflict-free)
    unsigned short* tbl4 = (unsigned short*)(stg + NT * 89);  // 576 entries
    unsigned short* tbl6 = tbl4 + 576;                        // 832 entries
    const int tid = threadIdx.x;

    for (int idx = tid; idx < CF * CF * IPAD; idx += NT) sW[idx] = gWtp[idx];
    for (int idx = tid; idx < NM * CF * KPAD; idx += NT) sK[idx] = gK[idx];
    // index tables: stage offset for each element of one hi-res row image
    for (int ee = tid; ee < 576; ee += NT) {
        int px = ee / 9;
        int c = ee - px * 9;
        int b = px & 3;
        int lxr = px >> 2;
        int cat = (b < 3) ? 0 : 1;   // a==3 rows: same entry + 44 (cat 2/3)
        tbl4[ee] = (unsigned short)(lxr * 89 + cat * CF + c);
    }
    for (int ee = tid; ee < 832; ee += NT) {
        int px = ee / 13;
        int c = ee - px * 13;
        int b = px & 3;
        int lxr = px >> 2;
        int cat = (b < 3) ? 0 : 1;
        tbl6[ee] = (unsigned short)(lxr * 89 + cat * CF + 9 + c);
    }
    __syncthreads();

    const int tiles_x = W / TILE_W;
    const int tx0 = (blockIdx.x % tiles_x) * TILE_W;
    const int ty0 = (blockIdx.x / tiles_x) * TILE_H;
    const int lx = tid % TILE_W;
    const int ly = tid / TILE_W;
    const int w0 = tx0 + lx;
    const int h0 = ty0 + ly;
    const int wR = min(w0 + 1, W - 1);
    const int hD = min(h0 + 1, H - 1);
    const int p00 = h0 * W + w0;
    const int p01 = h0 * W + wR;
    const int p10 = hD * W + w0;
    const int p11 = hD * W + wR;

    // ---- preload: f00 -> regs + stage[0..21]; difference vectors -> stage ----
    // stage layout per thread: [0..21]=f00, [22..43]=dR, [44..65]=dD, [66..87]=d2
    float* myst = stg + tid * 89;
    ull f2[11];
    {
        float xv[CF];
        #pragma unroll
        for (int c = 0; c < CF; c++) {
            xv[c] = (c < 9) ? f4[p00 * 9 + c] : f6[p00 * 13 + (c - 9)];
            myst[c] = xv[c];
        }
        #pragma unroll
        for (int kk = 0; kk < 11; kk++) f2[kk] = pk2(xv[2 * kk], xv[2 * kk + 1]);
        #pragma unroll
        for (int c = 0; c < CF; c++) {
            float vR = (c < 9) ? f4[p01 * 9 + c] : f6[p01 * 13 + (c - 9)];
            float vD = (c < 9) ? f4[p10 * 9 + c] : f6[p10 * 13 + (c - 9)];
            float vX = (c < 9) ? f4[p11 * 9 + c] : f6[p11 * 13 + (c - 9)];
            myst[1 * CF + c] = vR - xv[c];                 // dR
            myst[2 * CF + c] = vD - xv[c];                 // dD
            myst[3 * CF + c] = vX - vR - vD + xv[c];       // d2
        }
    }

    // ---- ctx in difference basis: 4 matvecs ----
    ull ctx2[4][11];
    #pragma unroll
    for (int c4 = 0; c4 < 4; c4++)
        #pragma unroll
        for (int kk = 0; kk < 11; kk++) ctx2[c4][kk] = 0ULL;

    const ulonglong2* sK2 = (const ulonglong2*)sK;
    ctx_pass<0>(ctx2, sK2, myst, 0);            // ctx0 = m0 . f00
    ctx_pass<1>(ctx2, sK2, myst + CF, 1);       // e1   = m1 . dR
    ctx_pass<2>(ctx2, sK2, myst + 2 * CF, 2);   // e2   = m2 . dD
    ctx_pass<3>(ctx2, sK2, myst + 3 * CF, 3);   // e3   = m3 . d2

    // unpack to 88 scalar regs (upk2 aliases to reg pairs -> free)
    float ctx[4][CF];
    #pragma unroll
    for (int c4 = 0; c4 < 4; c4++)
        #pragma unroll
        for (int kk = 0; kk < 11; kk++) {
            float a, b;
            upk2(ctx2[c4][kk], a, b);
            ctx[c4][2 * kk] = a;
            ctx[c4][2 * kk + 1] = b;
        }

    // ---- bilinear: accumulate vs (ctx0,e1,e2,e3); derive cats in epilogue ----
    const ulonglong2* sW2 = (const ulonglong2*)sW;
    #pragma unroll 1
    for (int k = 0; k < CF; k++) {
        float o0 = 0.f, oE1 = 0.f, oE2 = 0.f, oE3 = 0.f;
        const ulonglong2* wbase = sW2 + k * (CF * 6);
        #pragma unroll
        for (int j = 0; j < CF; j++) {
            const ulonglong2* wr = wbase + j * 6;
            ulonglong2 t0 = wr[0], t1 = wr[1], t2 = wr[2];
            ull va = pmul(f2[0], t0.x);
            ull vb = pmul(f2[1], t0.y);
            va = pfma(f2[2], t1.x, va);
            vb = pfma(f2[3], t1.y, vb);
            va = pfma(f2[4], t2.x, va);
            vb = pfma(f2[5], t2.y, vb);
            ulonglong2 t3 = wr[3], t4 = wr[4];
            ull t10 = wr[5].x;
            va = pfma(f2[6], t3.x, va);
            vb = pfma(f2[7], t3.y, vb);
            va = pfma(f2[8], t4.x, va);
            vb = pfma(f2[9], t4.y, vb);
            va = pfma(f2[10], t10, va);
            ull vp = padd(va, vb);
            float a, b;
            upk2(vp, a, b);          // free: pair aliasing
            float v = a + b;         // 1 scalar fadd
            o0  += v * ctx[0][j];
            oE1 += v * ctx[1][j];
            oE2 += v * ctx[2][j];
            oE3 += v * ctx[3][j];
        }
        // derive categories + residual (f00[k] still resident in myst[k])
        float xk = myst[k];
        float c0 = o0 + xk;
        myst[0 * CF + k] = c0;                 // interior
        myst[1 * CF + k] = c0 + oE1;           // right edge
        myst[2 * CF + k] = c0 + oE2;           // bottom edge
        myst[3 * CF + k] = c0 + oE1 + oE2 + oE3;  // corner
    }
    __syncthreads();

    // ---- table-driven drain: pure smem->gmem copy, no div, no LDG ----
    const int Wr = W * 4;
    {   // out4: 64 px * 9 floats = 144 float4 per hi-res row
        const int QR = 144;
        for (int idx = tid; idx < TILE_H * 4 * QR; idx += NT) {
            int y = idx / QR;
            int q = idx - y * QR;
            int py = y >> 2;
            int base = py * (TILE_W * 89) + (((y & 3) == 3) ? 2 * CF : 0);
            ushort4 tb = *(const ushort4*)(tbl4 + q * 4);
            float4 v = make_float4(stg[base + tb.x], stg[base + tb.y],
                                   stg[base + tb.z], stg[base + tb.w]);
            int gy = ty0 * 4 + y;
            float4* dst = (float4*)(out + ((size_t)gy * Wr + (size_t)tx0 * 4) * 9);
            dst[q] = v;
        }
    }
    {   // out6: 64 px * 13 floats = 208 float4 per hi-res row
        const size_t N9 = (size_t)H * W * 16 * 9;
        const int QR = 208;
        for (int idx = tid; idx < TILE_H * 4 * QR; idx += NT) {
            int y = idx / QR;
            int q = idx - y * QR;
            int py = y >> 2;
            int base = py * (TILE_W * 89) + (((y & 3) == 3) ? 2 * CF : 0);
            ushort4 tb = *(const ushort4*)(tbl6 + q * 4);
            float4 v = make_float4(stg[base + tb.x], stg[base + tb.y],
                                   stg[base + tb.z], stg[base + tb.w]);
            int gy = ty0 * 4 + y;
            float4* dst = (float4*)(out + N9 + ((size_t)gy * Wr + (size_t)tx0 * 4) * 13);
            dst[q] = v;
        }
    }
}

extern "C" void kernel_launch(void* const* d_in, const int* in_sizes, int n_in,
                              void* d_out, int out_size) {
    const float* f4     = (const float*)d_in[0];
    const float* f6     = (const float*)d_in[1];
    const float* sh     = (const float*)d_in[2];
    const float* cg_agg = (const float*)d_in[3];
    const float* cg_tp  = (const float*)d_in[4];
    const float* w_agg  = (const float*)d_in[5];
    const float* w_tp   = (const float*)d_in[6];
    float* out = (float*)d_out;

    int HW = in_sizes[0] / 9;
    int W = (int)(sqrt((double)HW) + 0.5);
    int H = HW / W;

    prep_kernel<<<96, 128>>>(sh, cg_agg, cg_tp, w_agg, w_tp);

    // floats: sW 11616 + sK 2112 + stage 11392 + tables 704 = 25824
    int smemB = (CF * CF * IPAD + NM * CF * KPAD + NT * 89 + 704) * (int)sizeof(float);
    cudaFuncSetAttribute(main_kernel, cudaFuncAttributeMaxDynamicSharedMemorySize, smemB);
    int nblocks = HW / NT;
    main_kernel<<<nblocks, NT, smemB>>>(f4, f6, out, H, W);
}